// round 10
// baseline (speedup 1.0000x reference)
#include <cuda_runtime.h>
#include <math.h>

// Problem constants (fixed by the reference)
#define S_SZ  4096
#define D_SZ  300
#define C_SZ  4
#define D4    75            // float4 per embedding row
#define NB    128           // blocks (fully resident)
#define RPB   32            // sequence rows per block
#define NT    512           // threads per block (16 warps)
#define NLEAF 16            // barrier tree: 16 leaves x 8 blocks

// Scratch (device globals; no allocation allowed)
__device__ float    g_part1[D_SZ * NB];   // transposed [d][b]
__device__ float    g_dense[D_SZ];
__device__ float    g_mid[D_SZ];
__device__ float    g_t[D_SZ];
__device__ float    g_w2mid[C_SZ];
__device__ float    g_psum[NB];           // per-block unnormalized exp sums
__device__ float    g_y[C_SZ * NB];       // per-block W2 . (unnorm weighted sum)

// Barrier state: every counter on its own 128B line (no spin/arrival ping-pong)
struct __align__(128) PadCtr { unsigned v; unsigned pad[31]; };
__device__ PadCtr g_leaf[5][NLEAF];       // zero-init; self-resetting
__device__ PadCtr g_root[5];              // zero-init; self-resetting
__device__ PadCtr g_gen[5];               // monotonic (graph-replay safe)

__device__ __forceinline__ float warp_sum(float p) {
    #pragma unroll
    for (int o = 16; o > 0; o >>= 1) p += __shfl_xor_sync(0xFFFFFFFFu, p, o);
    return p;
}

// Tree grid barrier #i. Arrival: acq_rel leaf atomic (8 blocks/leaf); last of
// leaf does acq_rel root atomic; last of root bumps gen (release). Waiters
// spin with nanosleep on ld.acquire of gen. Counters self-reset pre-bump;
// each block arrives exactly once per launch -> graph-replay safe.
__device__ __forceinline__ void gbar(int i, int b) {
    __syncthreads();
    if (threadIdx.x == 0) {
        unsigned g;
        asm volatile("ld.relaxed.gpu.u32 %0,[%1];"
                     : "=r"(g) : "l"(&g_gen[i].v) : "memory");
        unsigned old;
        asm volatile("atom.acq_rel.gpu.add.u32 %0,[%1],%2;"
                     : "=r"(old) : "l"(&g_leaf[i][b >> 3].v), "r"(1u) : "memory");
        bool released = false;
        if (old == 7) {                                  // last of this leaf
            asm volatile("st.relaxed.gpu.u32 [%0],%1;"
                         :: "l"(&g_leaf[i][b >> 3].v), "r"(0u) : "memory");
            unsigned r;
            asm volatile("atom.acq_rel.gpu.add.u32 %0,[%1],%2;"
                         : "=r"(r) : "l"(&g_root[i].v), "r"(1u) : "memory");
            if (r == NLEAF - 1) {                        // last leaf overall
                asm volatile("st.relaxed.gpu.u32 [%0],%1;"
                             :: "l"(&g_root[i].v), "r"(0u) : "memory");
                unsigned d;
                asm volatile("atom.acq_rel.gpu.add.u32 %0,[%1],%2;"
                             : "=r"(d) : "l"(&g_gen[i].v), "r"(1u) : "memory");
                released = true;
            }
        }
        if (!released) {
            unsigned cur;
            do {
                __nanosleep(32);
                asm volatile("ld.acquire.gpu.u32 %0,[%1];"
                             : "=r"(cur) : "l"(&g_gen[i].v) : "memory");
            } while (cur == g);
        }
    }
    __syncthreads();
}

__device__ __forceinline__ float dot4(float4 a, float4 b) {
    return fmaf(a.x, b.x, fmaf(a.y, b.y, fmaf(a.z, b.z, a.w * b.w)));
}

// Warp dot of a preloaded 300-float row (3 float4/lane) with an smem vector.
__device__ __forceinline__ float warp_dot_pre(float4 a0, float4 a1, float4 a2,
                                              const float4* __restrict__ v4,
                                              int lane) {
    float p = dot4(a0, v4[lane]) + dot4(a1, v4[lane + 32]);
    if (lane < D4 - 64) p += dot4(a2, v4[lane + 64]);
    return warp_sum(p);
}

// ---------------------------------------------------------------------------
__global__ __launch_bounds__(NT)
void fused(const int* __restrict__ x, const float* __restrict__ emb,
           const float* __restrict__ W1, const float* __restrict__ b1,
           const float* __restrict__ Wb, const float* __restrict__ bb,
           const float* __restrict__ W2, const float* __restrict__ b2,
           float* __restrict__ out)
{
    const int b = blockIdx.x, tid = threadIdx.x;
    const int lane = tid & 31, w = tid >> 5;

    __shared__ float4 s_emb[RPB][D4];   // staged embedding rows (38.4 KB)
    __shared__ float4 s_acc[4][D4];
    __shared__ float4 s_v4[D4 + 1];
    __shared__ float  s_sc[RPB];
    __shared__ float  s_e[RPB];
    __shared__ float  s_bc;
    __shared__ int    s_idx[RPB];
    float* s_v = (float*)s_v4;

    if (tid < RPB) s_idx[tid] = __ldg(&x[b * RPB + tid]);
    __syncthreads();

    // ---- Register preloads (concurrent with the DRAM gather, no barrier dep)
    const float4 z = make_float4(0.f, 0.f, 0.f, 0.f);
    float4 wA0 = z, wA1 = z, wA2 = z;       // W1 row d (warps 0-2)
    float4 wB0 = z, wB1 = z, wB2 = z;       // Wb row d (warps 0-2)
    float4 wC0 = z, wC1 = z, wC2 = z;       // W2 row (warps 4-7)
    float  b1v = 0.f;
    const int drow = w * NB + b;            // matvec row owned by warps 0-2
    if (w < 3 && drow < D_SZ) {
        const float4* wr1 = (const float4*)(W1 + (long)drow * D_SZ);
        const float4* wrb = (const float4*)(Wb + (long)drow * D_SZ);
        wA0 = __ldg(&wr1[lane]);  wA1 = __ldg(&wr1[lane + 32]);
        wB0 = __ldg(&wrb[lane]);  wB1 = __ldg(&wrb[lane + 32]);
        if (lane < D4 - 64) { wA2 = __ldg(&wr1[lane + 64]); wB2 = __ldg(&wrb[lane + 64]); }
        b1v = __ldg(&b1[drow]);
    }
    if (w >= 4 && w < 4 + C_SZ) {
        const float4* wr2 = (const float4*)(W2 + (long)(w - 4) * D_SZ);
        wC0 = __ldg(&wr2[lane]);  wC1 = __ldg(&wr2[lane + 32]);
        if (lane < D4 - 64) wC2 = __ldg(&wr2[lane + 64]);
    }

    const float4* emb4 = (const float4*)emb;

    // ---- Phase A: gather 32 rows (DRAM) -> smem stage + per-block partials
    if (tid < D_SZ) {
        const int c = tid % D4, g = tid / D4;
        float4 acc = z;
        #pragma unroll
        for (int k = 0; k < 8; k++) {
            const int r = g * 8 + k;
            float4 v = __ldg(&emb4[(long)s_idx[r] * D4 + c]);
            s_emb[r][c] = v;
            acc.x += v.x; acc.y += v.y; acc.z += v.z; acc.w += v.w;
        }
        s_acc[g][c] = acc;
    }
    __syncthreads();
    if (tid < D4) {
        float4 t0 = s_acc[0][tid], t1 = s_acc[1][tid];
        float4 t2 = s_acc[2][tid], t3 = s_acc[3][tid];
        g_part1[(4 * tid + 0) * NB + b] = (t0.x + t1.x) + (t2.x + t3.x);
        g_part1[(4 * tid + 1) * NB + b] = (t0.y + t1.y) + (t2.y + t3.y);
        g_part1[(4 * tid + 2) * NB + b] = (t0.z + t1.z) + (t2.z + t3.z);
        g_part1[(4 * tid + 3) * NB + b] = (t0.w + t1.w) + (t2.w + t3.w);
    }
    gbar(0, b);

    // ---- Phase B: dense[d] (warp-per-d, spread: block b owns d = w*128+b)
    if (w < 3 && drow < D_SZ) {
        const float* pp = g_part1 + (long)drow * NB;
        float v = (pp[lane] + pp[lane + 32]) + (pp[lane + 64] + pp[lane + 96]);
        v = warp_sum(v);
        if (lane == 0) g_dense[drow] = v * (1.0f / S_SZ);
    }
    gbar(1, b);

    // ---- Phase C: mid = W1*dense + b1 (preloaded rows, smem vector)
    for (int d = tid; d < D_SZ; d += NT) s_v[d] = g_dense[d];
    __syncthreads();
    if (w < 3 && drow < D_SZ) {
        float p = warp_dot_pre(wA0, wA1, wA2, s_v4, lane);
        if (lane == 0) g_mid[drow] = p + b1v;
    }
    gbar(2, b);

    // ---- Phase D: t = Wb*mid; block 0 warps 4-7 also compute W2*mid
    for (int d = tid; d < D_SZ; d += NT) s_v[d] = g_mid[d];
    __syncthreads();
    if (w < 3 && drow < D_SZ) {
        float p = warp_dot_pre(wB0, wB1, wB2, s_v4, lane);
        if (lane == 0) g_t[drow] = p;
    } else if (b == 0 && w >= 4 && w < 4 + C_SZ) {
        float p = warp_dot_pre(wC0, wC1, wC2, s_v4, lane);
        if (lane == 0) g_w2mid[w - 4] = p;
    }
    gbar(3, b);

    // ---- Phase E: scores/exp/psum + unnormalized weighted sum + y, all smem
    for (int d = tid; d < D_SZ; d += NT) s_v[d] = g_t[d];
    __syncthreads();
    {
        const float bias = __ldg(bb);
        #pragma unroll
        for (int j = 0; j < 2; j++) {
            const int r = w * 2 + j;
            float p = dot4(s_emb[r][lane], s_v4[lane])
                    + dot4(s_emb[r][lane + 32], s_v4[lane + 32]);
            if (lane < D4 - 64) p += dot4(s_emb[r][lane + 64], s_v4[lane + 64]);
            p = warp_sum(p);
            if (lane == 0) s_sc[r] = p + bias;
        }
    }
    __syncthreads();
    if (w == 0) {                   // scores tiny -> unshifted exp exact-safe
        float e = expf(s_sc[lane]);
        s_e[lane] = e;
        float ps = warp_sum(e);
        if (lane == 0) g_psum[b] = ps;
    }
    __syncthreads();
    if (tid < D_SZ) {               // weighted sum with raw e (pure smem)
        const int c = tid % D4, g = tid / D4;
        float4 acc = z;
        #pragma unroll
        for (int k = 0; k < 8; k++) {
            const int r = g * 8 + k;
            const float wt = s_e[r];
            float4 v = s_emb[r][c];
            acc.x = fmaf(wt, v.x, acc.x); acc.y = fmaf(wt, v.y, acc.y);
            acc.z = fmaf(wt, v.z, acc.z); acc.w = fmaf(wt, v.w, acc.w);
        }
        s_acc[g][c] = acc;
    }
    __syncthreads();
    if (tid < D4) {                 // t consumed: reuse s_v4 for the partial
        float4 t0 = s_acc[0][tid], t1 = s_acc[1][tid];
        float4 t2 = s_acc[2][tid], t3 = s_acc[3][tid];
        s_v4[tid] = make_float4((t0.x + t1.x) + (t2.x + t3.x),
                                (t0.y + t1.y) + (t2.y + t3.y),
                                (t0.z + t1.z) + (t2.z + t3.z),
                                (t0.w + t1.w) + (t2.w + t3.w));
    }
    __syncthreads();
    if (w >= 4 && w < 4 + C_SZ) {   // y_b[c] = W2[c,:] . block_partial
        float p = warp_dot_pre(wC0, wC1, wC2, s_v4, lane);
        if (lane == 0) g_y[(w - 4) * NB + b] = p;
    }
    gbar(4, b);

    // ---- Phase F: redundant total (identical order), rewards, logits
    if (w == 0) {
        float v = (g_psum[lane] + g_psum[lane + 32])
                + (g_psum[lane + 64] + g_psum[lane + 96]);
        v = warp_sum(v);
        if (lane == 0) s_bc = 1.0f / v;
    }
    __syncthreads();
    const float inv = s_bc;
    if (tid < RPB)
        out[C_SZ + b * RPB + tid] = s_e[tid] * inv;

    if (b == 0 && w < C_SZ) {
        const float* yy = g_y + (long)w * NB;
        float v = (yy[lane] + yy[lane + 32]) + (yy[lane + 64] + yy[lane + 96]);
        v = warp_sum(v);
        if (lane == 0)
            out[w] = g_w2mid[w] + v * inv * (1.0f / S_SZ) + __ldg(&b2[w]);
    }
}

// ---------------------------------------------------------------------------
extern "C" void kernel_launch(void* const* d_in, const int* in_sizes, int n_in,
                              void* d_out, int out_size)
{
    const int*   x   = (const int*)  d_in[0];
    const float* emb = (const float*)d_in[1];
    const float* W1  = (const float*)d_in[2];
    const float* b1  = (const float*)d_in[3];
    const float* Wb  = (const float*)d_in[4];
    const float* bb  = (const float*)d_in[5];
    const float* W2  = (const float*)d_in[6];
    const float* b2  = (const float*)d_in[7];
    float* out = (float*)d_out;   // out[0:4] = output, out[4:4100] = reward

    fused<<<NB, NT>>>(x, emb, W1, b1, Wb, bb, W2, b2, out);
}

// round 11
// speedup vs baseline: 1.0762x; 1.0762x over previous
#include <cuda_runtime.h>
#include <math.h>

// Problem constants (fixed by the reference)
#define S_SZ  4096
#define D_SZ  300
#define C_SZ  4
#define D4    75            // float4 per embedding row
#define NB    128           // blocks (fully resident)
#define RPB   32            // sequence rows per block
#define NT    512           // threads per block (16 warps)

// Scratch (device globals; no allocation allowed)
__device__ float    g_part1[D_SZ * NB];   // transposed [d][b]
__device__ float    g_dense[D_SZ];
__device__ float    g_mid[D_SZ];
__device__ float    g_t[D_SZ];
__device__ float    g_w2mid[C_SZ];
__device__ float    g_psum[NB];           // per-block unnormalized exp sums
__device__ float    g_y[C_SZ * NB];       // per-block W2 . (unnorm weighted sum)
__device__ unsigned g_cnt[3];             // grid barrier counts (self-reset)
__device__ unsigned g_gen[3];             // grid barrier gens (monotonic)

// Mini-barrier state (8 arrivals each), padded to own lines
struct __align__(128) PadCtr { unsigned v; unsigned pad[31]; };
__device__ PadCtr g_sbc[2];               // counts (self-reset)
__device__ PadCtr g_sbg[2];               // gens (monotonic)

__device__ __forceinline__ float warp_sum(float p) {
    #pragma unroll
    for (int o = 16; o > 0; o >>= 1) p += __shfl_xor_sync(0xFFFFFFFFu, p, o);
    return p;
}

// Flat grid barrier (R7-proven). acq_rel arrival, nanosleep acquire spin.
__device__ __forceinline__ void gbar(int i) {
    __syncthreads();
    if (threadIdx.x == 0) {
        unsigned g;
        asm volatile("ld.relaxed.gpu.u32 %0,[%1];"
                     : "=r"(g) : "l"(&g_gen[i]) : "memory");
        unsigned old;
        asm volatile("atom.acq_rel.gpu.add.u32 %0,[%1],%2;"
                     : "=r"(old) : "l"(&g_cnt[i]), "r"(1u) : "memory");
        if (old == NB - 1) {
            asm volatile("st.relaxed.gpu.u32 [%0],%1;"
                         :: "l"(&g_cnt[i]), "r"(0u) : "memory");
            unsigned d;
            asm volatile("atom.acq_rel.gpu.add.u32 %0,[%1],%2;"
                         : "=r"(d) : "l"(&g_gen[i]), "r"(1u) : "memory");
        } else {
            unsigned cur;
            do {
                __nanosleep(32);
                asm volatile("ld.acquire.gpu.u32 %0,[%1];"
                             : "=r"(cur) : "l"(&g_gen[i]) : "memory");
            } while (cur == g);
        }
    }
    __syncthreads();
}

// Mini-barrier primitives (8 participants). Thread 0 only.
__device__ __forceinline__ void sb_arrive(int i) {
    unsigned old;
    asm volatile("atom.acq_rel.gpu.add.u32 %0,[%1],%2;"
                 : "=r"(old) : "l"(&g_sbc[i].v), "r"(1u) : "memory");
    if (old == 7) {
        asm volatile("st.relaxed.gpu.u32 [%0],%1;"
                     :: "l"(&g_sbc[i].v), "r"(0u) : "memory");
        unsigned d;
        asm volatile("atom.acq_rel.gpu.add.u32 %0,[%1],%2;"
                     : "=r"(d) : "l"(&g_sbg[i].v), "r"(1u) : "memory");
    }
}
__device__ __forceinline__ void sb_spin(int i, unsigned snap) {
    unsigned cur;
    do {
        __nanosleep(32);
        asm volatile("ld.acquire.gpu.u32 %0,[%1];"
                     : "=r"(cur) : "l"(&g_sbg[i].v) : "memory");
    } while (cur == snap);
}

__device__ __forceinline__ float dot4(float4 a, float4 b) {
    return fmaf(a.x, b.x, fmaf(a.y, b.y, fmaf(a.z, b.z, a.w * b.w)));
}

// Warp dot of a preloaded 300-float row (3 float4/lane) with an smem vector.
__device__ __forceinline__ float warp_dot_pre(float4 a0, float4 a1, float4 a2,
                                              const float4* __restrict__ v4,
                                              int lane) {
    float p = dot4(a0, v4[lane]) + dot4(a1, v4[lane + 32]);
    if (lane < D4 - 64) p += dot4(a2, v4[lane + 64]);
    return warp_sum(p);
}

// ---------------------------------------------------------------------------
__global__ __launch_bounds__(NT)
void fused(const int* __restrict__ x, const float* __restrict__ emb,
           const float* __restrict__ W1, const float* __restrict__ b1,
           const float* __restrict__ Wb, const float* __restrict__ bb,
           const float* __restrict__ W2, const float* __restrict__ b2,
           float* __restrict__ out)
{
    const int b = blockIdx.x, tid = threadIdx.x;
    const int lane = tid & 31, w = tid >> 5;

    __shared__ float4 s_emb[RPB][D4];   // staged embedding rows (38.4 KB)
    __shared__ float4 s_acc[4][D4];
    __shared__ float4 s_v4[D4 + 1];
    __shared__ float  s_sc[RPB];
    __shared__ float  s_e[RPB];
    __shared__ float  s_bc;
    __shared__ int    s_idx[RPB];
    float* s_v = (float*)s_v4;

    // Mini-barrier generation snapshots. Taken BEFORE bar0 arrival: bumps are
    // gated behind bar0 release, which needs this block's arrival, which
    // happens after this read -> snapshot always pre-bump. Thread 0 only.
    unsigned snapA = 0, snapB = 0;
    if (tid == 0) {
        asm volatile("ld.relaxed.gpu.u32 %0,[%1];" : "=r"(snapA) : "l"(&g_sbg[0].v) : "memory");
        asm volatile("ld.relaxed.gpu.u32 %0,[%1];" : "=r"(snapB) : "l"(&g_sbg[1].v) : "memory");
    }

    if (tid < RPB) s_idx[tid] = __ldg(&x[b * RPB + tid]);
    __syncthreads();

    // ---- Register preloads (concurrent with the DRAM gather)
    const float4 z = make_float4(0.f, 0.f, 0.f, 0.f);
    // Chain-matrix rows: blocks 0-7 hold all of W1, blocks 8-15 all of Wb.
    // Warp cw (0..99) owns rows 3cw..3cw+2 (9 float4 per lane).
    const int cw = (b & 7) * 16 + w;
    float4 p00=z,p01=z,p02=z, p10=z,p11=z,p12=z, p20=z,p21=z,p22=z;
    float bv0=0.f, bv1=0.f, bv2=0.f;
    if (b < 16 && cw < 100) {
        const float* Ws = (b < 8) ? W1 : Wb;
        const float4* r0 = (const float4*)(Ws + (long)(3 * cw + 0) * D_SZ);
        const float4* r1 = (const float4*)(Ws + (long)(3 * cw + 1) * D_SZ);
        const float4* r2 = (const float4*)(Ws + (long)(3 * cw + 2) * D_SZ);
        p00 = __ldg(&r0[lane]); p01 = __ldg(&r0[lane + 32]);
        p10 = __ldg(&r1[lane]); p11 = __ldg(&r1[lane + 32]);
        p20 = __ldg(&r2[lane]); p21 = __ldg(&r2[lane + 32]);
        if (lane < D4 - 64) {
            p02 = __ldg(&r0[lane + 64]);
            p12 = __ldg(&r1[lane + 64]);
            p22 = __ldg(&r2[lane + 64]);
        }
        if (b < 8) {
            bv0 = __ldg(&b1[3 * cw + 0]);
            bv1 = __ldg(&b1[3 * cw + 1]);
            bv2 = __ldg(&b1[3 * cw + 2]);
        }
    }
    float4 wC0 = z, wC1 = z, wC2 = z;       // W2 row (warps 4-7, all blocks)
    if (w >= 4 && w < 4 + C_SZ) {
        const float4* wr2 = (const float4*)(W2 + (long)(w - 4) * D_SZ);
        wC0 = __ldg(&wr2[lane]);  wC1 = __ldg(&wr2[lane + 32]);
        if (lane < D4 - 64) wC2 = __ldg(&wr2[lane + 64]);
    }

    const float4* emb4 = (const float4*)emb;

    // ---- Phase A: gather 32 rows (DRAM) -> smem stage + per-block partials
    if (tid < D_SZ) {
        const int c = tid % D4, g = tid / D4;
        float4 acc = z;
        #pragma unroll
        for (int k = 0; k < 8; k++) {
            const int r = g * 8 + k;
            float4 v = __ldg(&emb4[(long)s_idx[r] * D4 + c]);
            s_emb[r][c] = v;
            acc.x += v.x; acc.y += v.y; acc.z += v.z; acc.w += v.w;
        }
        s_acc[g][c] = acc;
    }
    __syncthreads();
    if (tid < D4) {
        float4 t0 = s_acc[0][tid], t1 = s_acc[1][tid];
        float4 t2 = s_acc[2][tid], t3 = s_acc[3][tid];
        g_part1[(4 * tid + 0) * NB + b] = (t0.x + t1.x) + (t2.x + t3.x);
        g_part1[(4 * tid + 1) * NB + b] = (t0.y + t1.y) + (t2.y + t3.y);
        g_part1[(4 * tid + 2) * NB + b] = (t0.z + t1.z) + (t2.z + t3.z);
        g_part1[(4 * tid + 3) * NB + b] = (t0.w + t1.w) + (t2.w + t3.w);
    }
    gbar(0);

    // ---- Chain: G1 (blocks 0-7) dense + mid; G2 (blocks 8-15) t + W2*mid.
    if (b < 8) {
        // dense rows [b*38, b*38+38), warp-per-d, coalesced
        for (int d0 = w; d0 < 38; d0 += 16) {
            const int d = b * 38 + d0;
            if (d < D_SZ) {
                const float* pp = g_part1 + (long)d * NB;
                float v = (pp[lane] + pp[lane + 32]) + (pp[lane + 64] + pp[lane + 96]);
                v = warp_sum(v);
                if (lane == 0) g_dense[d] = v * (1.0f / S_SZ);
            }
        }
        __syncthreads();
        if (tid == 0) { sb_arrive(0); sb_spin(0, snapA); }   // 8-way mini-bar
        __syncthreads();
        for (int d = tid; d < D_SZ; d += NT) s_v[d] = g_dense[d];
        __syncthreads();
        if (cw < 100) {                      // mid rows from registers
            float m0 = warp_dot_pre(p00, p01, p02, s_v4, lane);
            float m1 = warp_dot_pre(p10, p11, p12, s_v4, lane);
            float m2 = warp_dot_pre(p20, p21, p22, s_v4, lane);
            if (lane == 0) {
                g_mid[3 * cw + 0] = m0 + bv0;
                g_mid[3 * cw + 1] = m1 + bv1;
                g_mid[3 * cw + 2] = m2 + bv2;
            }
        }
        __syncthreads();
        if (tid == 0) sb_arrive(1);          // signal mid ready (no wait)
    } else if (b < 16) {
        if (tid == 0) sb_spin(1, snapB);     // wait for mid
        __syncthreads();
        for (int d = tid; d < D_SZ; d += NT) s_v[d] = g_mid[d];
        __syncthreads();
        if (cw < 100) {                      // t rows from registers
            float t0 = warp_dot_pre(p00, p01, p02, s_v4, lane);
            float t1 = warp_dot_pre(p10, p11, p12, s_v4, lane);
            float t2 = warp_dot_pre(p20, p21, p22, s_v4, lane);
            if (lane == 0) {
                g_t[3 * cw + 0] = t0;
                g_t[3 * cw + 1] = t1;
                g_t[3 * cw + 2] = t2;
            }
        }
        if (b == 8 && w >= 4 && w < 4 + C_SZ) {   // w2mid (s_v holds mid)
            float p = warp_dot_pre(wC0, wC1, wC2, s_v4, lane);
            if (lane == 0) g_w2mid[w - 4] = p;
        }
    }
    gbar(1);

    // ---- Phase E: scores/exp/psum + unnormalized weighted sum + y, all smem
    for (int d = tid; d < D_SZ; d += NT) s_v[d] = g_t[d];
    __syncthreads();
    {
        const float bias = __ldg(bb);
        #pragma unroll
        for (int j = 0; j < 2; j++) {
            const int r = w * 2 + j;
            float p = dot4(s_emb[r][lane], s_v4[lane])
                    + dot4(s_emb[r][lane + 32], s_v4[lane + 32]);
            if (lane < D4 - 64) p += dot4(s_emb[r][lane + 64], s_v4[lane + 64]);
            p = warp_sum(p);
            if (lane == 0) s_sc[r] = p + bias;
        }
    }
    __syncthreads();
    if (w == 0) {                   // scores tiny -> unshifted exp exact-safe
        float e = expf(s_sc[lane]);
        s_e[lane] = e;
        float ps = warp_sum(e);
        if (lane == 0) g_psum[b] = ps;
    }
    __syncthreads();
    if (tid < D_SZ) {               // weighted sum with raw e (pure smem)
        const int c = tid % D4, g = tid / D4;
        float4 acc = z;
        #pragma unroll
        for (int k = 0; k < 8; k++) {
            const int r = g * 8 + k;
            const float wt = s_e[r];
            float4 v = s_emb[r][c];
            acc.x = fmaf(wt, v.x, acc.x); acc.y = fmaf(wt, v.y, acc.y);
            acc.z = fmaf(wt, v.z, acc.z); acc.w = fmaf(wt, v.w, acc.w);
        }
        s_acc[g][c] = acc;
    }
    __syncthreads();
    if (tid < D4) {                 // t consumed: reuse s_v4 for the partial
        float4 t0 = s_acc[0][tid], t1 = s_acc[1][tid];
        float4 t2 = s_acc[2][tid], t3 = s_acc[3][tid];
        s_v4[tid] = make_float4((t0.x + t1.x) + (t2.x + t3.x),
                                (t0.y + t1.y) + (t2.y + t3.y),
                                (t0.z + t1.z) + (t2.z + t3.z),
                                (t0.w + t1.w) + (t2.w + t3.w));
    }
    __syncthreads();
    if (w >= 4 && w < 4 + C_SZ) {   // y_b[c] = W2[c,:] . block_partial
        float p = warp_dot_pre(wC0, wC1, wC2, s_v4, lane);
        if (lane == 0) g_y[(w - 4) * NB + b] = p;
    }
    gbar(2);

    // ---- Final: redundant total (identical order), rewards, logits
    if (w == 0) {
        float v = (g_psum[lane] + g_psum[lane + 32])
                + (g_psum[lane + 64] + g_psum[lane + 96]);
        v = warp_sum(v);
        if (lane == 0) s_bc = 1.0f / v;
    }
    __syncthreads();
    const float inv = s_bc;
    if (tid < RPB)
        out[C_SZ + b * RPB + tid] = s_e[tid] * inv;

    if (b == 0 && w < C_SZ) {
        const float* yy = g_y + (long)w * NB;
        float v = (yy[lane] + yy[lane + 32]) + (yy[lane + 64] + yy[lane + 96]);
        v = warp_sum(v);
        if (lane == 0)
            out[w] = g_w2mid[w] + v * inv * (1.0f / S_SZ) + __ldg(&b2[w]);
    }
}

// ---------------------------------------------------------------------------
extern "C" void kernel_launch(void* const* d_in, const int* in_sizes, int n_in,
                              void* d_out, int out_size)
{
    const int*   x   = (const int*)  d_in[0];
    const float* emb = (const float*)d_in[1];
    const float* W1  = (const float*)d_in[2];
    const float* b1  = (const float*)d_in[3];
    const float* Wb  = (const float*)d_in[4];
    const float* bb  = (const float*)d_in[5];
    const float* W2  = (const float*)d_in[6];
    const float* b2  = (const float*)d_in[7];
    float* out = (float*)d_out;   // out[0:4] = output, out[4:4100] = reward

    fused<<<NB, NT>>>(x, emb, W1, b1, Wb, bb, W2, b2, out);
}